// round 3
// baseline (speedup 1.0000x reference)
#include <cuda_runtime.h>
#include <math.h>

#define NMAT 256
#define DIM 64
#define DD 4096
#define K_LOG 32
#define K_EXP 28
#define CSTRIDE 40

// ---------------- device scratch (no allocations allowed) ----------------
__device__ float g_L[NMAT * DD];      // log_X
__device__ float g_Z[NMAT * DD];      // log_X + M
__device__ float g_numK[NMAT * DD];   // sum_j W[j,k] * L_j
__device__ float g_W[NMAT * NMAT];
__device__ float g_sq[NMAT];
__device__ float g_s[NMAT];
__device__ float g_rs[NMAT];          // row sums of W
__device__ float g_cs[NMAT];          // col sums of W
__device__ float g_logc[NMAT * CSTRIDE];
__device__ float g_expc[NMAT * CSTRIDE];

// ---------------- packed f32x2 helpers (Blackwell dual-rate fp32) ----------------
__device__ __forceinline__ unsigned long long ffma2(unsigned long long a,
                                                    unsigned long long b,
                                                    unsigned long long c) {
    unsigned long long d;
    asm("fma.rn.f32x2 %0, %1, %2, %3;" : "=l"(d) : "l"(a), "l"(b), "l"(c));
    return d;
}
__device__ __forceinline__ unsigned long long bcast2(float x) {
    unsigned long long d;
    unsigned int xi = __float_as_uint(x);
    asm("mov.b64 %0, {%1, %1};" : "=l"(d) : "r"(xi));
    return d;
}
__device__ __forceinline__ float2 unpk(unsigned long long v) {
    unsigned int a, b;
    asm("mov.b64 {%0, %1}, %2;" : "=r"(a), "=r"(b) : "l"(v));
    return make_float2(__uint_as_float(a), __uint_as_float(b));
}

// ================= phase 0: per-matrix log-Chebyshev coefficients =================
__global__ __launch_bounds__(64) void prep_log(const float* __restrict__ X) {
    __shared__ float red[64];
    int b = blockIdx.x, t = threadIdx.x;
    const float* Xb = X + (size_t)b * DD;
    float rs_ = 0.f;
    for (int c = 0; c < DIM; ++c) rs_ += fabsf(Xb[t * DIM + c]);
    red[t] = rs_;
    __syncthreads();
    if (t == 0) {
        float mx = 0.f;
        for (int i = 0; i < 64; ++i) mx = fmaxf(mx, red[i]);
        float a = 0.49f, bb = mx + 1e-3f;
        if (bb < 0.6f) bb = 0.6f;
        float m = 0.5f * (a + bb), h = 0.5f * (bb - a);
        float beta = h / m;
        float q = (1.f - sqrtf(fmaxf(1.f - beta * beta, 0.f))) / beta;
        float* cc = g_logc + b * CSTRIDE;
        cc[0] = logf(m) - logf(1.f + q * q);
        float qk = 1.f, sgn = 1.f;
        for (int k = 1; k <= K_LOG; ++k) {
            qk *= q;
            cc[k] = 2.f * sgn * qk / (float)k;
            sgn = -sgn;
        }
        cc[38] = m;
        cc[39] = h;
    }
}

// ================= Clenshaw step: Bp_new = fac*Ys*Bc - Bp + ck*I =================
// Ys symmetric: Ys(i,k) = Ys[k*64+i] -> both operands read row-contiguous.
__device__ __forceinline__ void chebstep(const float* __restrict__ Ys,
                                         const float* __restrict__ Bc,
                                         float* __restrict__ Bp,
                                         int i0, int j0, float ck, float fac) {
    unsigned long long acc[4][2];
#pragma unroll
    for (int c = 0; c < 4; ++c) { acc[c][0] = 0ull; acc[c][1] = 0ull; }

#pragma unroll 8
    for (int k = 0; k < DIM; ++k) {
        const ulonglong2 av = *reinterpret_cast<const ulonglong2*>(Ys + k * DIM + i0);
        const float4 bv = *reinterpret_cast<const float4*>(Bc + k * DIM + j0);
        unsigned long long b0 = bcast2(bv.x), b1 = bcast2(bv.y);
        unsigned long long b2 = bcast2(bv.z), b3 = bcast2(bv.w);
        acc[0][0] = ffma2(av.x, b0, acc[0][0]); acc[0][1] = ffma2(av.y, b0, acc[0][1]);
        acc[1][0] = ffma2(av.x, b1, acc[1][0]); acc[1][1] = ffma2(av.y, b1, acc[1][1]);
        acc[2][0] = ffma2(av.x, b2, acc[2][0]); acc[2][1] = ffma2(av.y, b2, acc[2][1]);
        acc[3][0] = ffma2(av.x, b3, acc[3][0]); acc[3][1] = ffma2(av.y, b3, acc[3][1]);
    }
#pragma unroll
    for (int c = 0; c < 4; ++c) {
#pragma unroll
        for (int r2 = 0; r2 < 2; ++r2) {
            float2 p = unpk(acc[c][r2]);
            int i = i0 + 2 * r2;
            int j = j0 + c;
            float v0 = fmaf(fac, p.x, -Bp[i * DIM + j]);
            float v1 = fmaf(fac, p.y, -Bp[(i + 1) * DIM + j]);
            if (i == j) v0 += ck;
            if (i + 1 == j) v1 += ck;
            Bp[i * DIM + j] = v0;
            Bp[(i + 1) * DIM + j] = v1;
        }
    }
    __syncthreads();
}

// ================= Chebyshev matrix function via Clenshaw =================
__device__ __forceinline__ void cheb_body(const float* __restrict__ src,
                                          const float* __restrict__ coefs,
                                          int K, float* __restrict__ dst) {
    __shared__ float sm[3 * DD];  // exactly 48KB
    float* Ys = sm;
    float* B1 = sm + DD;
    float* B2 = sm + 2 * DD;
    int b = blockIdx.x, tid = threadIdx.x;
    const float* cc = coefs + b * CSTRIDE;
    const float m = cc[38], h = cc[39];
    const float invh = 1.f / h;
    const float cK = cc[K];
    const float* sb = src + (size_t)b * DD;

#pragma unroll
    for (int u = 0; u < 4; ++u) {
        int e = (u * 256 + tid) * 4;
        float4 x = *reinterpret_cast<const float4*>(sb + e);
        int i = e >> 6;
        int jb = e & 63;
        float4 y, bi;
        y.x = (x.x - ((jb + 0) == i ? m : 0.f)) * invh;
        y.y = (x.y - ((jb + 1) == i ? m : 0.f)) * invh;
        y.z = (x.z - ((jb + 2) == i ? m : 0.f)) * invh;
        y.w = (x.w - ((jb + 3) == i ? m : 0.f)) * invh;
        bi.x = ((jb + 0) == i) ? cK : 0.f;
        bi.y = ((jb + 1) == i) ? cK : 0.f;
        bi.z = ((jb + 2) == i) ? cK : 0.f;
        bi.w = ((jb + 3) == i) ? cK : 0.f;
        *reinterpret_cast<float4*>(Ys + e) = y;
        *reinterpret_cast<float4*>(B1 + e) = bi;
        *reinterpret_cast<float4*>(B2 + e) = make_float4(0.f, 0.f, 0.f, 0.f);
    }
    __syncthreads();

    int i0 = (tid >> 4) << 2, j0 = (tid & 15) << 2;
    float* Bc = B1;
    float* Bp = B2;
    for (int k = K - 1; k >= 1; --k) {
        chebstep(Ys, Bc, Bp, i0, j0, cc[k], 2.f);
        float* tp = Bc; Bc = Bp; Bp = tp;
    }
    chebstep(Ys, Bc, Bp, i0, j0, cc[0], 1.f);

    float* db = dst + (size_t)b * DD;
#pragma unroll
    for (int u = 0; u < 4; ++u) {
        int e = (u * 256 + tid) * 4;
        *reinterpret_cast<float4*>(db + e) = *reinterpret_cast<const float4*>(Bp + e);
    }
}

__global__ __launch_bounds__(256) void cheb_log_kernel(const float* __restrict__ X) {
    cheb_body(X, g_logc, K_LOG, g_L);
}
__global__ __launch_bounds__(256) void cheb_exp_kernel(float* __restrict__ out) {
    cheb_body(g_Z, g_expc, K_EXP, out);
}

// ================= per-matrix sq / s =================
__global__ __launch_bounds__(256) void stats_kernel() {
    __shared__ float r1[256], r2[256];
    int b = blockIdx.x, tid = threadIdx.x;
    const float* Lb = g_L + (size_t)b * DD;
    float a = 0.f, s = 0.f;
#pragma unroll 4
    for (int t = 0; t < 16; ++t) {
        float v = Lb[tid * 16 + t];
        a = fmaf(v, v, a);
        s += v;
    }
    r1[tid] = a;
    r2[tid] = s;
    __syncthreads();
    for (int off = 128; off > 0; off >>= 1) {
        if (tid < off) { r1[tid] += r1[tid + off]; r2[tid] += r2[tid + off]; }
        __syncthreads();
    }
    if (tid == 0) { g_sq[b] = r1[0]; g_s[b] = r2[0]; }
}

// ================= gram + W fused =================
#define LSTR 132
__global__ __launch_bounds__(256) void gramW_kernel(const float* __restrict__ bwp) {
    __shared__ float Li[32 * LSTR], Lj[32 * LSTR];
    int tid = threadIdx.x;
    int i0 = blockIdx.y * 32, j0 = blockIdx.x * 32;
    int ti = tid >> 4, tj = tid & 15;
    float a00 = 0.f, a01 = 0.f, a10 = 0.f, a11 = 0.f;

    for (int mc = 0; mc < 32; ++mc) {
#pragma unroll
        for (int u = 0; u < 4; ++u) {
            int f4 = tid * 4 + u;              // 0..1023
            int row = f4 >> 5, c4 = f4 & 31;
            *reinterpret_cast<float4*>(Li + row * LSTR + c4 * 4) =
                *reinterpret_cast<const float4*>(g_L + (size_t)(i0 + row) * DD + mc * 128 + c4 * 4);
            *reinterpret_cast<float4*>(Lj + row * LSTR + c4 * 4) =
                *reinterpret_cast<const float4*>(g_L + (size_t)(j0 + row) * DD + mc * 128 + c4 * 4);
        }
        __syncthreads();
#pragma unroll 8
        for (int m4 = 0; m4 < 32; ++m4) {
            float4 x0 = *reinterpret_cast<const float4*>(Li + (2 * ti) * LSTR + m4 * 4);
            float4 x1 = *reinterpret_cast<const float4*>(Li + (2 * ti + 1) * LSTR + m4 * 4);
            float4 y0 = *reinterpret_cast<const float4*>(Lj + (2 * tj) * LSTR + m4 * 4);
            float4 y1 = *reinterpret_cast<const float4*>(Lj + (2 * tj + 1) * LSTR + m4 * 4);
            a00 = fmaf(x0.x, y0.x, fmaf(x0.y, y0.y, fmaf(x0.z, y0.z, fmaf(x0.w, y0.w, a00))));
            a01 = fmaf(x0.x, y1.x, fmaf(x0.y, y1.y, fmaf(x0.z, y1.z, fmaf(x0.w, y1.w, a01))));
            a10 = fmaf(x1.x, y0.x, fmaf(x1.y, y0.y, fmaf(x1.z, y0.z, fmaf(x1.w, y0.w, a10))));
            a11 = fmaf(x1.x, y1.x, fmaf(x1.y, y1.y, fmaf(x1.z, y1.z, fmaf(x1.w, y1.w, a11))));
        }
        __syncthreads();
    }
    float bw = *bwp;
    float coef = -0.5f / (bw * bw);
    const float eps = 1e-7f;
    int gi0 = i0 + 2 * ti, gj0 = j0 + 2 * tj;
#pragma unroll
    for (int r = 0; r < 2; ++r) {
#pragma unroll
        for (int c = 0; c < 2; ++c) {
            int gi = gi0 + r, gj = gj0 + c;
            float g = (r == 0) ? (c == 0 ? a00 : a01) : (c == 0 ? a10 : a11);
            float pds = g_sq[gi] + g_sq[gj] - 2.f * g
                        + 2.f * eps * (g_s[gj] - g_s[gi]) + eps * eps * 4096.f;
            g_W[gi * NMAT + gj] = expf(coef * pds);
        }
    }
}

// ================= row/col sums of W =================
__global__ __launch_bounds__(256) void sums_kernel() {
    __shared__ float r1[256], r2[256];
    int k = blockIdx.x, t = threadIdx.x;
    r1[t] = g_W[k * NMAT + t];
    r2[t] = g_W[t * NMAT + k];
    __syncthreads();
    for (int off = 128; off > 0; off >>= 1) {
        if (t < off) { r1[t] += r1[t + off]; r2[t] += r2[t + off]; }
        __syncthreads();
    }
    if (t == 0) { g_rs[k] = r1[0]; g_cs[k] = r2[0]; }
}

// ================= numK[k,c] = sum_j W[j,k]*L[j,c] =================
__global__ __launch_bounds__(256) void numK_kernel() {
    __shared__ float Ws[64 * 64], Ls[64 * 64];
    int tid = threadIdx.x;
    int c0 = blockIdx.x * 64, k0 = blockIdx.y * 64;
    int i0 = (tid >> 4) << 2, j0 = (tid & 15) << 2;
    unsigned long long acc[4][2];
#pragma unroll
    for (int c = 0; c < 4; ++c) { acc[c][0] = 0ull; acc[c][1] = 0ull; }

    for (int jc = 0; jc < 4; ++jc) {
#pragma unroll
        for (int u = 0; u < 4; ++u) {
            int f4 = tid * 4 + u;             // 0..1023
            int jj = f4 >> 4, q4 = f4 & 15;
            *reinterpret_cast<float4*>(Ws + jj * 64 + q4 * 4) =
                *reinterpret_cast<const float4*>(g_W + (size_t)(jc * 64 + jj) * NMAT + k0 + q4 * 4);
            *reinterpret_cast<float4*>(Ls + jj * 64 + q4 * 4) =
                *reinterpret_cast<const float4*>(g_L + (size_t)(jc * 64 + jj) * DD + c0 + q4 * 4);
        }
        __syncthreads();
#pragma unroll 8
        for (int jj = 0; jj < 64; ++jj) {
            const ulonglong2 av = *reinterpret_cast<const ulonglong2*>(Ws + jj * 64 + i0);
            const float4 bv = *reinterpret_cast<const float4*>(Ls + jj * 64 + j0);
            unsigned long long b0 = bcast2(bv.x), b1 = bcast2(bv.y);
            unsigned long long b2 = bcast2(bv.z), b3 = bcast2(bv.w);
            acc[0][0] = ffma2(av.x, b0, acc[0][0]); acc[0][1] = ffma2(av.y, b0, acc[0][1]);
            acc[1][0] = ffma2(av.x, b1, acc[1][0]); acc[1][1] = ffma2(av.y, b1, acc[1][1]);
            acc[2][0] = ffma2(av.x, b2, acc[2][0]); acc[2][1] = ffma2(av.y, b2, acc[2][1]);
            acc[3][0] = ffma2(av.x, b3, acc[3][0]); acc[3][1] = ffma2(av.y, b3, acc[3][1]);
        }
        __syncthreads();
    }
#pragma unroll
    for (int c = 0; c < 4; ++c) {
#pragma unroll
        for (int r2 = 0; r2 < 2; ++r2) {
            float2 p = unpk(acc[c][r2]);
            int kk = k0 + i0 + 2 * r2;
            int cc = c0 + j0 + c;
            g_numK[(size_t)kk * DD + cc] = p.x;
            g_numK[(size_t)(kk + 1) * DD + cc] = p.y;
        }
    }
}

// ================= Z = L*(1-cs/rs) + numK/rs, bounds + exp coefficients =================
__global__ __launch_bounds__(256) void prep_exp() {
    __shared__ float absP[256], diaP[256];
    __shared__ float hiA[64], loA[64];
    __shared__ float mh[2];
    int b = blockIdx.x, tid = threadIdx.x;
    const float* Lb = g_L + (size_t)b * DD;
    const float* Nb = g_numK + (size_t)b * DD;
    float* Zb = g_Z + (size_t)b * DD;
    float rs_ = g_rs[b], cs_ = g_cs[b];
    float fL = 1.f - cs_ / rs_;
    float fN = 1.f / rs_;
    int r = tid >> 2, q = tid & 3;
    float pa = 0.f, pd = 0.f;
#pragma unroll 4
    for (int t = 0; t < 16; ++t) {
        int cidx = q * 16 + t;
        int e = r * 64 + cidx;
        float z = fmaf(fL, Lb[e], fN * Nb[e]);
        Zb[e] = z;
        pa += fabsf(z);
        if (cidx == r) pd = z;
    }
    absP[tid] = pa;
    diaP[tid] = pd;
    __syncthreads();
    if (tid < 64) {
        float ra = absP[4 * tid] + absP[4 * tid + 1] + absP[4 * tid + 2] + absP[4 * tid + 3];
        float dv = diaP[4 * tid] + diaP[4 * tid + 1] + diaP[4 * tid + 2] + diaP[4 * tid + 3];
        float off = ra - fabsf(dv);
        hiA[tid] = dv + off;
        loA[tid] = dv - off;
    }
    __syncthreads();
    if (tid == 0) {
        float lo = loA[0], hi = hiA[0];
        for (int i = 1; i < 64; ++i) { lo = fminf(lo, loA[i]); hi = fmaxf(hi, hiA[i]); }
        float m = 0.5f * (lo + hi);
        float h = 0.5f * (hi - lo) + 0.01f;
        if (h < 0.05f) h = 0.05f;
        mh[0] = m;
        mh[1] = h;
        g_expc[b * CSTRIDE + 38] = m;
        g_expc[b * CSTRIDE + 39] = h;
    }
    __syncthreads();
    if (tid <= K_EXP) {
        float m = mh[0], h = mh[1];
        float h2 = 0.5f * h;
        int k = tid;
        float term = 1.f;
        for (int i = 1; i <= k; ++i) term *= h2 / (float)i;
        float ssum = term;
        for (int t = 1; t <= 48; ++t) {
            term *= (h2 * h2) / ((float)t * (float)(k + t));
            ssum += term;
            if (term < ssum * 1e-10f) break;
        }
        g_expc[b * CSTRIDE + k] = (k == 0 ? 1.f : 2.f) * expf(m) * ssum;
    }
}

// ================= launch =================
extern "C" void kernel_launch(void* const* d_in, const int* in_sizes, int n_in,
                              void* d_out, int out_size) {
    const float* X = (const float*)d_in[0];
    const float* bw = (const float*)d_in[1];
    float* out = (float*)d_out;
    (void)in_sizes; (void)n_in; (void)out_size;

    prep_log<<<NMAT, 64>>>(X);
    cheb_log_kernel<<<NMAT, 256>>>(X);
    stats_kernel<<<NMAT, 256>>>();
    gramW_kernel<<<dim3(8, 8), 256>>>(bw);
    sums_kernel<<<NMAT, 256>>>();
    numK_kernel<<<dim3(64, 4), 256>>>();
    prep_exp<<<NMAT, 256>>>();
    cheb_exp_kernel<<<NMAT, 256>>>(out);
}

// round 7
// speedup vs baseline: 1.6863x; 1.6863x over previous
#include <cuda_runtime.h>
#include <math.h>

#define NMAT 256
#define DIM 64
#define DD 4096
#define K_LOG 22
#define K_EXP 18

// dynamic smem: Ys | B1 | B2 | extra(64 floats: coeffs + m,h)
#define SMEMX (3 * DD * 4 + 64 * 4)

// ---------------- device scratch (no allocations allowed) ----------------
__device__ float g_L[NMAT * DD];          // log_X
__device__ float g_numK[NMAT * DD];       // sum_j W[j,k] * L_j
__device__ float g_W[NMAT * NMAT];
__device__ float g_gramP[8 * NMAT * NMAT];// split-K partial gram
__device__ float g_sq[NMAT];
__device__ float g_s[NMAT];
__device__ float g_rs[NMAT];
__device__ float g_cs[NMAT];

// ---------------- packed f32x2 helpers ----------------
__device__ __forceinline__ unsigned long long ffma2(unsigned long long a,
                                                    unsigned long long b,
                                                    unsigned long long c) {
    unsigned long long d;
    asm("fma.rn.f32x2 %0, %1, %2, %3;" : "=l"(d) : "l"(a), "l"(b), "l"(c));
    return d;
}
__device__ __forceinline__ unsigned long long bcast2(float x) {
    unsigned long long d;
    unsigned int xi = __float_as_uint(x);
    asm("mov.b64 %0, {%1, %1};" : "=l"(d) : "r"(xi));
    return d;
}
__device__ __forceinline__ float2 unpk(unsigned long long v) {
    unsigned int a, b;
    asm("mov.b64 {%0, %1}, %2;" : "=r"(a), "=r"(b) : "l"(v));
    return make_float2(__uint_as_float(a), __uint_as_float(b));
}

// ================= Clenshaw step: Bp_new = fac*Ys*Bc - Bp + ck*I =================
__device__ __forceinline__ void chebstep(const float* __restrict__ Ys,
                                         const float* __restrict__ Bc,
                                         float* __restrict__ Bp,
                                         int i0, int j0, float ck, float fac) {
    unsigned long long acc[4][2];
#pragma unroll
    for (int c = 0; c < 4; ++c) { acc[c][0] = 0ull; acc[c][1] = 0ull; }

#pragma unroll 8
    for (int k = 0; k < DIM; ++k) {
        const ulonglong2 av = *reinterpret_cast<const ulonglong2*>(Ys + k * DIM + i0);
        const float4 bv = *reinterpret_cast<const float4*>(Bc + k * DIM + j0);
        unsigned long long b0 = bcast2(bv.x), b1 = bcast2(bv.y);
        unsigned long long b2 = bcast2(bv.z), b3 = bcast2(bv.w);
        acc[0][0] = ffma2(av.x, b0, acc[0][0]); acc[0][1] = ffma2(av.y, b0, acc[0][1]);
        acc[1][0] = ffma2(av.x, b1, acc[1][0]); acc[1][1] = ffma2(av.y, b1, acc[1][1]);
        acc[2][0] = ffma2(av.x, b2, acc[2][0]); acc[2][1] = ffma2(av.y, b2, acc[2][1]);
        acc[3][0] = ffma2(av.x, b3, acc[3][0]); acc[3][1] = ffma2(av.y, b3, acc[3][1]);
    }
#pragma unroll
    for (int c = 0; c < 4; ++c) {
#pragma unroll
        for (int r2 = 0; r2 < 2; ++r2) {
            float2 p = unpk(acc[c][r2]);
            int i = i0 + 2 * r2;
            int j = j0 + c;
            float v0 = fmaf(fac, p.x, -Bp[i * DIM + j]);
            float v1 = fmaf(fac, p.y, -Bp[(i + 1) * DIM + j]);
            if (i == j) v0 += ck;
            if (i + 1 == j) v1 += ck;
            Bp[i * DIM + j] = v0;
            Bp[(i + 1) * DIM + j] = v1;
        }
    }
    __syncthreads();
}

// scale Ys in place: Ys = (Ysraw - m*I)/h ; init B1 = cK*I, B2 = 0
__device__ __forceinline__ void scale_init(float* Ys, float* B1, float* B2,
                                           int tid, float m, float invh, float cK) {
#pragma unroll
    for (int u = 0; u < 4; ++u) {
        int e = (u * 256 + tid) * 4;
        float4 x = *reinterpret_cast<const float4*>(Ys + e);
        int i = e >> 6;
        int jb = e & 63;
        float4 y, bi;
        y.x = (x.x - ((jb + 0) == i ? m : 0.f)) * invh;
        y.y = (x.y - ((jb + 1) == i ? m : 0.f)) * invh;
        y.z = (x.z - ((jb + 2) == i ? m : 0.f)) * invh;
        y.w = (x.w - ((jb + 3) == i ? m : 0.f)) * invh;
        bi.x = ((jb + 0) == i) ? cK : 0.f;
        bi.y = ((jb + 1) == i) ? cK : 0.f;
        bi.z = ((jb + 2) == i) ? cK : 0.f;
        bi.w = ((jb + 3) == i) ? cK : 0.f;
        *reinterpret_cast<float4*>(Ys + e) = y;
        *reinterpret_cast<float4*>(B1 + e) = bi;
        *reinterpret_cast<float4*>(B2 + e) = make_float4(0.f, 0.f, 0.f, 0.f);
    }
    __syncthreads();
}

// ================= cheb_log: load X, Gershgorin, coeffs, Clenshaw, store L + stats =================
__global__ __launch_bounds__(256) void cheb_log_kernel(const float* __restrict__ X) {
    extern __shared__ float sm[];
    float* Ys = sm;
    float* B1 = sm + DD;
    float* B2 = sm + 2 * DD;
    float* extra = sm + 3 * DD;       // [0..K_LOG] coeffs, [36]=m, [37]=h
    int b = blockIdx.x, tid = threadIdx.x;
    const float* sb = X + (size_t)b * DD;

    // load raw X into Ys + per-thread abs row-segment sum
    int r = tid >> 2, q = tid & 3;
    float pa = 0.f;
#pragma unroll
    for (int u = 0; u < 4; ++u) {
        int cb = q * 16 + u * 4;
        float4 x = *reinterpret_cast<const float4*>(sb + r * 64 + cb);
        *reinterpret_cast<float4*>(Ys + r * 64 + cb) = x;
        pa += fabsf(x.x) + fabsf(x.y) + fabsf(x.z) + fabsf(x.w);
    }
    B1[tid] = pa;
    __syncthreads();
    if (tid < 64) {
        B1[1024 + tid] = B1[4 * tid] + B1[4 * tid + 1] + B1[4 * tid + 2] + B1[4 * tid + 3];
    }
    __syncthreads();
    if (tid == 0) {
        float mx = 0.f;
        for (int i = 0; i < 64; ++i) mx = fmaxf(mx, B1[1024 + i]);
        float a = 0.49f, bb = mx + 1e-3f;
        if (bb < 0.6f) bb = 0.6f;
        extra[36] = 0.5f * (a + bb);
        extra[37] = 0.5f * (bb - a);
    }
    __syncthreads();
    if (tid <= K_LOG) {
        float m = extra[36], h = extra[37];
        float beta = h / m;
        float s = sqrtf(fmaxf(1.f - beta * beta, 0.f));
        float qz = (1.f - s) / beta;
        if (tid == 0) extra[0] = logf(m) - logf(1.f + qz * qz);
        else {
            float qk = exp2f((float)tid * log2f(qz));
            extra[tid] = 2.f * ((tid & 1) ? 1.f : -1.f) * qk / (float)tid;
        }
    }
    __syncthreads();

    const float m = extra[36], invh = 1.f / extra[37];
    scale_init(Ys, B1, B2, tid, m, invh, extra[K_LOG]);

    int i0 = (tid >> 4) << 2, j0 = (tid & 15) << 2;
    float* Bc = B1;
    float* Bp = B2;
    for (int k = K_LOG - 1; k >= 1; --k) {
        chebstep(Ys, Bc, Bp, i0, j0, extra[k], 2.f);
        float* tp = Bc; Bc = Bp; Bp = tp;
    }
    chebstep(Ys, Bc, Bp, i0, j0, extra[0], 1.f);

    // store L + fused stats (sq, s)
    float* db = g_L + (size_t)b * DD;
    float sqa = 0.f, ssum = 0.f;
#pragma unroll
    for (int u = 0; u < 4; ++u) {
        int e = (u * 256 + tid) * 4;
        float4 v = *reinterpret_cast<const float4*>(Bp + e);
        *reinterpret_cast<float4*>(db + e) = v;
        sqa = fmaf(v.x, v.x, fmaf(v.y, v.y, fmaf(v.z, v.z, fmaf(v.w, v.w, sqa))));
        ssum += v.x + v.y + v.z + v.w;
    }
    __syncthreads();            // Ys no longer needed -> reuse for reduce
    Ys[tid] = sqa;
    Ys[256 + tid] = ssum;
    __syncthreads();
    for (int off = 128; off > 0; off >>= 1) {
        if (tid < off) { Ys[tid] += Ys[tid + off]; Ys[256 + tid] += Ys[256 + tid + off]; }
        __syncthreads();
    }
    if (tid == 0) { g_sq[b] = Ys[0]; g_s[b] = Ys[256]; }
}

// ================= gram: split-K GEMM, f32x2 packed along k (no broadcasts) =================
#define GST 68
__global__ __launch_bounds__(256) void gram_kernel() {
    __shared__ float Ti[64 * GST], Tj[64 * GST];
    int tid = threadIdx.x;
    int j0g = blockIdx.x * 64, i0g = blockIdx.y * 64, z = blockIdx.z; // k-slice of 512
    int ti = tid >> 4, tj = tid & 15;
    int i0 = ti * 4, j0 = tj * 4;

    unsigned long long acc[4][4];
#pragma unroll
    for (int a = 0; a < 4; ++a)
#pragma unroll
        for (int c = 0; c < 4; ++c) acc[a][c] = 0ull;

    for (int ch = 0; ch < 8; ++ch) {
        int kbase = z * 512 + ch * 64;
#pragma unroll
        for (int u = 0; u < 4; ++u) {
            int f4 = u * 256 + tid;
            int row = f4 >> 4, c4 = f4 & 15;
            *reinterpret_cast<float4*>(Ti + row * GST + c4 * 4) =
                *reinterpret_cast<const float4*>(g_L + (size_t)(i0g + row) * DD + kbase + c4 * 4);
            *reinterpret_cast<float4*>(Tj + row * GST + c4 * 4) =
                *reinterpret_cast<const float4*>(g_L + (size_t)(j0g + row) * DD + kbase + c4 * 4);
        }
        __syncthreads();
#pragma unroll 4
        for (int kk = 0; kk < 64; kk += 4) {
            ulonglong2 a0 = *reinterpret_cast<const ulonglong2*>(Ti + (i0 + 0) * GST + kk);
            ulonglong2 a1 = *reinterpret_cast<const ulonglong2*>(Ti + (i0 + 1) * GST + kk);
            ulonglong2 a2 = *reinterpret_cast<const ulonglong2*>(Ti + (i0 + 2) * GST + kk);
            ulonglong2 a3 = *reinterpret_cast<const ulonglong2*>(Ti + (i0 + 3) * GST + kk);
            ulonglong2 b0 = *reinterpret_cast<const ulonglong2*>(Tj + (j0 + 0) * GST + kk);
            ulonglong2 b1 = *reinterpret_cast<const ulonglong2*>(Tj + (j0 + 1) * GST + kk);
            ulonglong2 b2 = *reinterpret_cast<const ulonglong2*>(Tj + (j0 + 2) * GST + kk);
            ulonglong2 b3 = *reinterpret_cast<const ulonglong2*>(Tj + (j0 + 3) * GST + kk);
            acc[0][0] = ffma2(a0.x, b0.x, acc[0][0]); acc[0][0] = ffma2(a0.y, b0.y, acc[0][0]);
            acc[0][1] = ffma2(a0.x, b1.x, acc[0][1]); acc[0][1] = ffma2(a0.y, b1.y, acc[0][1]);
            acc[0][2] = ffma2(a0.x, b2.x, acc[0][2]); acc[0][2] = ffma2(a0.y, b2.y, acc[0][2]);
            acc[0][3] = ffma2(a0.x, b3.x, acc[0][3]); acc[0][3] = ffma2(a0.y, b3.y, acc[0][3]);
            acc[1][0] = ffma2(a1.x, b0.x, acc[1][0]); acc[1][0] = ffma2(a1.y, b0.y, acc[1][0]);
            acc[1][1] = ffma2(a1.x, b1.x, acc[1][1]); acc[1][1] = ffma2(a1.y, b1.y, acc[1][1]);
            acc[1][2] = ffma2(a1.x, b2.x, acc[1][2]); acc[1][2] = ffma2(a1.y, b2.y, acc[1][2]);
            acc[1][3] = ffma2(a1.x, b3.x, acc[1][3]); acc[1][3] = ffma2(a1.y, b3.y, acc[1][3]);
            acc[2][0] = ffma2(a2.x, b0.x, acc[2][0]); acc[2][0] = ffma2(a2.y, b0.y, acc[2][0]);
            acc[2][1] = ffma2(a2.x, b1.x, acc[2][1]); acc[2][1] = ffma2(a2.y, b1.y, acc[2][1]);
            acc[2][2] = ffma2(a2.x, b2.x, acc[2][2]); acc[2][2] = ffma2(a2.y, b2.y, acc[2][2]);
            acc[2][3] = ffma2(a2.x, b3.x, acc[2][3]); acc[2][3] = ffma2(a2.y, b3.y, acc[2][3]);
            acc[3][0] = ffma2(a3.x, b0.x, acc[3][0]); acc[3][0] = ffma2(a3.y, b0.y, acc[3][0]);
            acc[3][1] = ffma2(a3.x, b1.x, acc[3][1]); acc[3][1] = ffma2(a3.y, b1.y, acc[3][1]);
            acc[3][2] = ffma2(a3.x, b2.x, acc[3][2]); acc[3][2] = ffma2(a3.y, b2.y, acc[3][2]);
            acc[3][3] = ffma2(a3.x, b3.x, acc[3][3]); acc[3][3] = ffma2(a3.y, b3.y, acc[3][3]);
        }
        __syncthreads();
    }
#pragma unroll
    for (int ii = 0; ii < 4; ++ii) {
        float4 o;
        float2 p0 = unpk(acc[ii][0]); o.x = p0.x + p0.y;
        float2 p1 = unpk(acc[ii][1]); o.y = p1.x + p1.y;
        float2 p2 = unpk(acc[ii][2]); o.z = p2.x + p2.y;
        float2 p3 = unpk(acc[ii][3]); o.w = p3.x + p3.y;
        *reinterpret_cast<float4*>(g_gramP + (size_t)z * 65536 +
                                   (size_t)(i0g + i0 + ii) * NMAT + j0g + j0) = o;
    }
}

// ================= W from gram partials =================
__global__ __launch_bounds__(256) void W_kernel(const float* __restrict__ bwp) {
    int i = blockIdx.x, j = threadIdx.x;
    float g = 0.f;
#pragma unroll
    for (int z = 0; z < 8; ++z) g += g_gramP[(size_t)z * 65536 + (size_t)i * NMAT + j];
    float bw = *bwp;
    float coef = -0.5f / (bw * bw);
    const float eps = 1e-7f;
    float pds = g_sq[i] + g_sq[j] - 2.f * g + 2.f * eps * (g_s[j] - g_s[i]) + eps * eps * 4096.f;
    g_W[(size_t)i * NMAT + j] = expf(coef * pds);
}

// ================= row/col sums of W =================
__global__ __launch_bounds__(256) void sums_kernel() {
    __shared__ float r1[256], r2[256];
    int k = blockIdx.x, t = threadIdx.x;
    r1[t] = g_W[(size_t)k * NMAT + t];
    r2[t] = g_W[(size_t)t * NMAT + k];
    __syncthreads();
    for (int off = 128; off > 0; off >>= 1) {
        if (t < off) { r1[t] += r1[t + off]; r2[t] += r2[t + off]; }
        __syncthreads();
    }
    if (t == 0) { g_rs[k] = r1[0]; g_cs[k] = r2[0]; }
}

// ================= numK[k,c] = sum_j W[j,k]*L[j,c] =================
__global__ __launch_bounds__(256) void numK_kernel() {
    __shared__ float Ws[64 * 64], Ls[64 * 64];
    int tid = threadIdx.x;
    int c0 = blockIdx.x * 64, k0 = blockIdx.y * 64;
    int i0 = (tid >> 4) << 2, j0 = (tid & 15) << 2;
    unsigned long long acc[4][2];
#pragma unroll
    for (int c = 0; c < 4; ++c) { acc[c][0] = 0ull; acc[c][1] = 0ull; }

    for (int jc = 0; jc < 4; ++jc) {
#pragma unroll
        for (int u = 0; u < 4; ++u) {
            int f4 = tid * 4 + u;
            int jj = f4 >> 4, q4 = f4 & 15;
            *reinterpret_cast<float4*>(Ws + jj * 64 + q4 * 4) =
                *reinterpret_cast<const float4*>(g_W + (size_t)(jc * 64 + jj) * NMAT + k0 + q4 * 4);
            *reinterpret_cast<float4*>(Ls + jj * 64 + q4 * 4) =
                *reinterpret_cast<const float4*>(g_L + (size_t)(jc * 64 + jj) * DD + c0 + q4 * 4);
        }
        __syncthreads();
#pragma unroll 8
        for (int jj = 0; jj < 64; ++jj) {
            const ulonglong2 av = *reinterpret_cast<const ulonglong2*>(Ws + jj * 64 + i0);
            const float4 bv = *reinterpret_cast<const float4*>(Ls + jj * 64 + j0);
            unsigned long long b0 = bcast2(bv.x), b1 = bcast2(bv.y);
            unsigned long long b2 = bcast2(bv.z), b3 = bcast2(bv.w);
            acc[0][0] = ffma2(av.x, b0, acc[0][0]); acc[0][1] = ffma2(av.y, b0, acc[0][1]);
            acc[1][0] = ffma2(av.x, b1, acc[1][0]); acc[1][1] = ffma2(av.y, b1, acc[1][1]);
            acc[2][0] = ffma2(av.x, b2, acc[2][0]); acc[2][1] = ffma2(av.y, b2, acc[2][1]);
            acc[3][0] = ffma2(av.x, b3, acc[3][0]); acc[3][1] = ffma2(av.y, b3, acc[3][1]);
        }
        __syncthreads();
    }
#pragma unroll
    for (int c = 0; c < 4; ++c) {
#pragma unroll
        for (int r2 = 0; r2 < 2; ++r2) {
            float2 p = unpk(acc[c][r2]);
            int kk = k0 + i0 + 2 * r2;
            int cc = c0 + j0 + c;
            g_numK[(size_t)kk * DD + cc] = p.x;
            g_numK[(size_t)(kk + 1) * DD + cc] = p.y;
        }
    }
}

// ================= cheb_exp: build Z in smem, bounds, Bessel coeffs, Clenshaw =================
__global__ __launch_bounds__(256) void cheb_exp_kernel(float* __restrict__ out) {
    extern __shared__ float sm[];
    float* Ys = sm;
    float* B1 = sm + DD;
    float* B2 = sm + 2 * DD;
    float* extra = sm + 3 * DD;
    int b = blockIdx.x, tid = threadIdx.x;
    const float* Lb = g_L + (size_t)b * DD;
    const float* Nb = g_numK + (size_t)b * DD;
    float rs_ = g_rs[b], cs_ = g_cs[b];
    float fL = 1.f - cs_ / rs_;
    float fN = 1.f / rs_;

    // Z into Ys + Gershgorin pieces
    int r = tid >> 2, q = tid & 3;
    float pa = 0.f, pd = 0.f;
#pragma unroll
    for (int u = 0; u < 4; ++u) {
        int cb = q * 16 + u * 4;
        int e = r * 64 + cb;
        float4 l = *reinterpret_cast<const float4*>(Lb + e);
        float4 n = *reinterpret_cast<const float4*>(Nb + e);
        float4 z;
        z.x = fmaf(fL, l.x, fN * n.x);
        z.y = fmaf(fL, l.y, fN * n.y);
        z.z = fmaf(fL, l.z, fN * n.z);
        z.w = fmaf(fL, l.w, fN * n.w);
        *reinterpret_cast<float4*>(Ys + e) = z;
        pa += fabsf(z.x) + fabsf(z.y) + fabsf(z.z) + fabsf(z.w);
        if (r >= cb && r < cb + 4) {
            float zz[4] = {z.x, z.y, z.z, z.w};
            pd = zz[r - cb];
        }
    }
    B1[tid] = pa;
    B1[256 + tid] = pd;
    __syncthreads();
    if (tid < 64) {
        float ra = B1[4 * tid] + B1[4 * tid + 1] + B1[4 * tid + 2] + B1[4 * tid + 3];
        float dv = B1[256 + 4 * tid] + B1[256 + 4 * tid + 1] + B1[256 + 4 * tid + 2] + B1[256 + 4 * tid + 3];
        float off = ra - fabsf(dv);
        B1[512 + tid] = dv + off;   // hi
        B1[576 + tid] = dv - off;   // lo
    }
    __syncthreads();
    if (tid == 0) {
        float lo = B1[576], hi = B1[512];
        for (int i = 1; i < 64; ++i) { lo = fminf(lo, B1[576 + i]); hi = fmaxf(hi, B1[512 + i]); }
        float m = 0.5f * (lo + hi);
        float h = 0.5f * (hi - lo) + 0.01f;
        if (h < 0.05f) h = 0.05f;
        extra[36] = m;
        extra[37] = h;
    }
    __syncthreads();
    if (tid <= K_EXP) {
        float m = extra[36], h2 = 0.5f * extra[37];
        int k = tid;
        float term = 1.f;
        for (int i = 1; i <= k; ++i) term *= h2 / (float)i;
        float ssum = term;
        for (int t = 1; t <= 48; ++t) {
            term *= (h2 * h2) / ((float)t * (float)(k + t));
            ssum += term;
            if (term < ssum * 1e-10f) break;
        }
        extra[k] = (k == 0 ? 1.f : 2.f) * expf(m) * ssum;
    }
    __syncthreads();

    const float m = extra[36], invh = 1.f / extra[37];
    scale_init(Ys, B1, B2, tid, m, invh, extra[K_EXP]);

    int i0 = (tid >> 4) << 2, j0 = (tid & 15) << 2;
    float* Bc = B1;
    float* Bp = B2;
    for (int k = K_EXP - 1; k >= 1; --k) {
        chebstep(Ys, Bc, Bp, i0, j0, extra[k], 2.f);
        float* tp = Bc; Bc = Bp; Bp = tp;
    }
    chebstep(Ys, Bc, Bp, i0, j0, extra[0], 1.f);

    float* db = out + (size_t)b * DD;
#pragma unroll
    for (int u = 0; u < 4; ++u) {
        int e = (u * 256 + tid) * 4;
        *reinterpret_cast<float4*>(db + e) = *reinterpret_cast<const float4*>(Bp + e);
    }
}

// ================= launch =================
extern "C" void kernel_launch(void* const* d_in, const int* in_sizes, int n_in,
                              void* d_out, int out_size) {
    const float* X = (const float*)d_in[0];
    const float* bw = (const float*)d_in[1];
    float* out = (float*)d_out;
    (void)in_sizes; (void)n_in; (void)out_size;

    cudaFuncSetAttribute(cheb_log_kernel, cudaFuncAttributeMaxDynamicSharedMemorySize, SMEMX);
    cudaFuncSetAttribute(cheb_exp_kernel, cudaFuncAttributeMaxDynamicSharedMemorySize, SMEMX);

    cheb_log_kernel<<<NMAT, 256, SMEMX>>>(X);
    gram_kernel<<<dim3(4, 4, 8), 256>>>();
    W_kernel<<<NMAT, 256>>>(bw);
    sums_kernel<<<NMAT, 256>>>();
    numK_kernel<<<dim3(64, 4), 256>>>();
    cheb_exp_kernel<<<NMAT, 256, SMEMX>>>(out);
}

// round 8
// speedup vs baseline: 2.4458x; 1.4504x over previous
#include <cuda_runtime.h>
#include <math.h>

#define NMAT 256
#define DIM 64
#define DD 4096
#define K_LOG 16
#define K_EXP 12

// dynamic smem: Ys | B1 | B2 | extra(64 floats: coeffs + m,h)
#define SMEMX (3 * DD * 4 + 64 * 4)

// ---------------- device scratch (no allocations allowed) ----------------
__device__ float g_L[NMAT * DD];          // log_X
__device__ float g_numK[NMAT * DD];       // sum_j W[j,k] * L_j
__device__ float g_W[NMAT * NMAT];
__device__ float g_gramP[8 * NMAT * NMAT];// split-K partial gram
__device__ float g_sq[NMAT];
__device__ float g_s[NMAT];
__device__ float g_rs[NMAT];
__device__ float g_cs[NMAT];

// ---------------- packed f32x2 helpers ----------------
__device__ __forceinline__ unsigned long long ffma2(unsigned long long a,
                                                    unsigned long long b,
                                                    unsigned long long c) {
    unsigned long long d;
    asm("fma.rn.f32x2 %0, %1, %2, %3;" : "=l"(d) : "l"(a), "l"(b), "l"(c));
    return d;
}
__device__ __forceinline__ unsigned long long bcast2(float x) {
    unsigned long long d;
    unsigned int xi = __float_as_uint(x);
    asm("mov.b64 %0, {%1, %1};" : "=l"(d) : "r"(xi));
    return d;
}
__device__ __forceinline__ float2 unpk(unsigned long long v) {
    unsigned int a, b;
    asm("mov.b64 {%0, %1}, %2;" : "=r"(a), "=r"(b) : "l"(v));
    return make_float2(__uint_as_float(a), __uint_as_float(b));
}

// ============== Clenshaw step, 128 threads, 8x4 tile/thread ==============
// Bp_new = fac*Ys*Bc - Bp + ck*I.  Ys symmetric -> row-major reads for both.
__device__ __forceinline__ void chebstep(const float* __restrict__ Ys,
                                         const float* __restrict__ Bc,
                                         float* __restrict__ Bp,
                                         int i0, int j0, float ck, float fac) {
    // acc[ipair][j]: ipair covers rows (i0+2*ipair, i0+2*ipair+1)
    unsigned long long acc[4][4];
#pragma unroll
    for (int a = 0; a < 4; ++a)
#pragma unroll
        for (int c = 0; c < 4; ++c) acc[a][c] = 0ull;

#pragma unroll 8
    for (int k = 0; k < DIM; ++k) {
        const ulonglong2 a01 = *reinterpret_cast<const ulonglong2*>(Ys + k * DIM + i0);
        const ulonglong2 a23 = *reinterpret_cast<const ulonglong2*>(Ys + k * DIM + i0 + 4);
        const float4 bv = *reinterpret_cast<const float4*>(Bc + k * DIM + j0);
        unsigned long long b0 = bcast2(bv.x), b1 = bcast2(bv.y);
        unsigned long long b2 = bcast2(bv.z), b3 = bcast2(bv.w);
        acc[0][0] = ffma2(a01.x, b0, acc[0][0]); acc[1][0] = ffma2(a01.y, b0, acc[1][0]);
        acc[2][0] = ffma2(a23.x, b0, acc[2][0]); acc[3][0] = ffma2(a23.y, b0, acc[3][0]);
        acc[0][1] = ffma2(a01.x, b1, acc[0][1]); acc[1][1] = ffma2(a01.y, b1, acc[1][1]);
        acc[2][1] = ffma2(a23.x, b1, acc[2][1]); acc[3][1] = ffma2(a23.y, b1, acc[3][1]);
        acc[0][2] = ffma2(a01.x, b2, acc[0][2]); acc[1][2] = ffma2(a01.y, b2, acc[1][2]);
        acc[2][2] = ffma2(a23.x, b2, acc[2][2]); acc[3][2] = ffma2(a23.y, b2, acc[3][2]);
        acc[0][3] = ffma2(a01.x, b3, acc[0][3]); acc[1][3] = ffma2(a01.y, b3, acc[1][3]);
        acc[2][3] = ffma2(a23.x, b3, acc[2][3]); acc[3][3] = ffma2(a23.y, b3, acc[3][3]);
    }

    float2 p[4][4];
#pragma unroll
    for (int a = 0; a < 4; ++a)
#pragma unroll
        for (int c = 0; c < 4; ++c) p[a][c] = unpk(acc[a][c]);

#pragma unroll
    for (int r = 0; r < 8; ++r) {
        const int ip = r >> 1;
        const int i = i0 + r;
        float4 old = *reinterpret_cast<const float4*>(Bp + i * DIM + j0);
        const float a0 = (r & 1) ? p[ip][0].y : p[ip][0].x;
        const float a1 = (r & 1) ? p[ip][1].y : p[ip][1].x;
        const float a2 = (r & 1) ? p[ip][2].y : p[ip][2].x;
        const float a3 = (r & 1) ? p[ip][3].y : p[ip][3].x;
        float4 nv;
        nv.x = fmaf(fac, a0, -old.x);
        nv.y = fmaf(fac, a1, -old.y);
        nv.z = fmaf(fac, a2, -old.z);
        nv.w = fmaf(fac, a3, -old.w);
        if (i == j0 + 0) nv.x += ck;
        if (i == j0 + 1) nv.y += ck;
        if (i == j0 + 2) nv.z += ck;
        if (i == j0 + 3) nv.w += ck;
        *reinterpret_cast<float4*>(Bp + i * DIM + j0) = nv;
    }
    __syncthreads();
}

// scale Ys in place: Ys = (Ysraw - m*I)/h ; init B1 = cK*I, B2 = 0   (128 threads)
__device__ __forceinline__ void scale_init(float* Ys, float* B1, float* B2,
                                           int tid, float m, float invh, float cK) {
#pragma unroll
    for (int u = 0; u < 8; ++u) {
        int e = (u * 128 + tid) * 4;
        float4 x = *reinterpret_cast<const float4*>(Ys + e);
        int i = e >> 6;
        int jb = e & 63;
        float4 y, bi;
        y.x = (x.x - ((jb + 0) == i ? m : 0.f)) * invh;
        y.y = (x.y - ((jb + 1) == i ? m : 0.f)) * invh;
        y.z = (x.z - ((jb + 2) == i ? m : 0.f)) * invh;
        y.w = (x.w - ((jb + 3) == i ? m : 0.f)) * invh;
        bi.x = ((jb + 0) == i) ? cK : 0.f;
        bi.y = ((jb + 1) == i) ? cK : 0.f;
        bi.z = ((jb + 2) == i) ? cK : 0.f;
        bi.w = ((jb + 3) == i) ? cK : 0.f;
        *reinterpret_cast<float4*>(Ys + e) = y;
        *reinterpret_cast<float4*>(B1 + e) = bi;
        *reinterpret_cast<float4*>(B2 + e) = make_float4(0.f, 0.f, 0.f, 0.f);
    }
    __syncthreads();
}

// ===== cheb_log: load X, Gershgorin, coeffs, Clenshaw, store L + stats =====
__global__ __launch_bounds__(128) void cheb_log_kernel(const float* __restrict__ X) {
    extern __shared__ float sm[];
    float* Ys = sm;
    float* B1 = sm + DD;
    float* B2 = sm + 2 * DD;
    float* extra = sm + 3 * DD;       // [0..K] coeffs, [36]=m, [37]=h
    int b = blockIdx.x, tid = threadIdx.x;
    const float* sb = X + (size_t)b * DD;

    // load raw X into Ys + per-thread abs half-row sum
    int r = tid >> 1, q = tid & 1;
    float pa = 0.f;
#pragma unroll
    for (int u = 0; u < 8; ++u) {
        int cb = q * 32 + u * 4;
        float4 x = *reinterpret_cast<const float4*>(sb + r * 64 + cb);
        *reinterpret_cast<float4*>(Ys + r * 64 + cb) = x;
        pa += fabsf(x.x) + fabsf(x.y) + fabsf(x.z) + fabsf(x.w);
    }
    B1[tid] = pa;
    __syncthreads();
    if (tid < 64) B1[128 + tid] = B1[2 * tid] + B1[2 * tid + 1];
    __syncthreads();
    if (tid == 0) {
        float mx = 0.f;
        for (int i = 0; i < 64; ++i) mx = fmaxf(mx, B1[128 + i]);
        float a = 0.49f, bb = mx + 1e-3f;
        if (bb < 0.6f) bb = 0.6f;
        extra[36] = 0.5f * (a + bb);
        extra[37] = 0.5f * (bb - a);
    }
    __syncthreads();
    if (tid <= K_LOG) {
        float m = extra[36], h = extra[37];
        float beta = h / m;
        float s = sqrtf(fmaxf(1.f - beta * beta, 0.f));
        float qz = (1.f - s) / beta;
        if (tid == 0) extra[0] = logf(m) - logf(1.f + qz * qz);
        else {
            float qk = exp2f((float)tid * log2f(qz));
            extra[tid] = 2.f * ((tid & 1) ? 1.f : -1.f) * qk / (float)tid;
        }
    }
    __syncthreads();

    const float m = extra[36], invh = 1.f / extra[37];
    scale_init(Ys, B1, B2, tid, m, invh, extra[K_LOG]);

    const int i0 = (tid >> 4) << 3, j0 = (tid & 15) << 2;
    float* Bc = B1;
    float* Bp = B2;
    for (int k = K_LOG - 1; k >= 1; --k) {
        chebstep(Ys, Bc, Bp, i0, j0, extra[k], 2.f);
        float* tp = Bc; Bc = Bp; Bp = tp;
    }
    chebstep(Ys, Bc, Bp, i0, j0, extra[0], 1.f);

    // store L + fused stats (sq, s)
    float* db = g_L + (size_t)b * DD;
    float sqa = 0.f, ssum = 0.f;
#pragma unroll
    for (int u = 0; u < 8; ++u) {
        int e = (u * 128 + tid) * 4;
        float4 v = *reinterpret_cast<const float4*>(Bp + e);
        *reinterpret_cast<float4*>(db + e) = v;
        sqa = fmaf(v.x, v.x, fmaf(v.y, v.y, fmaf(v.z, v.z, fmaf(v.w, v.w, sqa))));
        ssum += v.x + v.y + v.z + v.w;
    }
    __syncthreads();            // Ys no longer needed -> reuse for reduce
    Ys[tid] = sqa;
    Ys[128 + tid] = ssum;
    __syncthreads();
    for (int off = 64; off > 0; off >>= 1) {
        if (tid < off) { Ys[tid] += Ys[tid + off]; Ys[128 + tid] += Ys[128 + tid + off]; }
        __syncthreads();
    }
    if (tid == 0) { g_sq[b] = Ys[0]; g_s[b] = Ys[128]; }
}

// ===== gram: split-K GEMM, f32x2 packed along k =====
#define GST 68
__global__ __launch_bounds__(256) void gram_kernel() {
    __shared__ float Ti[64 * GST], Tj[64 * GST];
    int tid = threadIdx.x;
    int j0g = blockIdx.x * 64, i0g = blockIdx.y * 64, z = blockIdx.z;
    int ti = tid >> 4, tj = tid & 15;
    int i0 = ti * 4, j0 = tj * 4;

    unsigned long long acc[4][4];
#pragma unroll
    for (int a = 0; a < 4; ++a)
#pragma unroll
        for (int c = 0; c < 4; ++c) acc[a][c] = 0ull;

    for (int ch = 0; ch < 8; ++ch) {
        int kbase = z * 512 + ch * 64;
#pragma unroll
        for (int u = 0; u < 4; ++u) {
            int f4 = u * 256 + tid;
            int row = f4 >> 4, c4 = f4 & 15;
            *reinterpret_cast<float4*>(Ti + row * GST + c4 * 4) =
                *reinterpret_cast<const float4*>(g_L + (size_t)(i0g + row) * DD + kbase + c4 * 4);
            *reinterpret_cast<float4*>(Tj + row * GST + c4 * 4) =
                *reinterpret_cast<const float4*>(g_L + (size_t)(j0g + row) * DD + kbase + c4 * 4);
        }
        __syncthreads();
#pragma unroll 4
        for (int kk = 0; kk < 64; kk += 4) {
            ulonglong2 a0 = *reinterpret_cast<const ulonglong2*>(Ti + (i0 + 0) * GST + kk);
            ulonglong2 a1 = *reinterpret_cast<const ulonglong2*>(Ti + (i0 + 1) * GST + kk);
            ulonglong2 a2 = *reinterpret_cast<const ulonglong2*>(Ti + (i0 + 2) * GST + kk);
            ulonglong2 a3 = *reinterpret_cast<const ulonglong2*>(Ti + (i0 + 3) * GST + kk);
            ulonglong2 b0 = *reinterpret_cast<const ulonglong2*>(Tj + (j0 + 0) * GST + kk);
            ulonglong2 b1 = *reinterpret_cast<const ulonglong2*>(Tj + (j0 + 1) * GST + kk);
            ulonglong2 b2 = *reinterpret_cast<const ulonglong2*>(Tj + (j0 + 2) * GST + kk);
            ulonglong2 b3 = *reinterpret_cast<const ulonglong2*>(Tj + (j0 + 3) * GST + kk);
            acc[0][0] = ffma2(a0.x, b0.x, acc[0][0]); acc[0][0] = ffma2(a0.y, b0.y, acc[0][0]);
            acc[0][1] = ffma2(a0.x, b1.x, acc[0][1]); acc[0][1] = ffma2(a0.y, b1.y, acc[0][1]);
            acc[0][2] = ffma2(a0.x, b2.x, acc[0][2]); acc[0][2] = ffma2(a0.y, b2.y, acc[0][2]);
            acc[0][3] = ffma2(a0.x, b3.x, acc[0][3]); acc[0][3] = ffma2(a0.y, b3.y, acc[0][3]);
            acc[1][0] = ffma2(a1.x, b0.x, acc[1][0]); acc[1][0] = ffma2(a1.y, b0.y, acc[1][0]);
            acc[1][1] = ffma2(a1.x, b1.x, acc[1][1]); acc[1][1] = ffma2(a1.y, b1.y, acc[1][1]);
            acc[1][2] = ffma2(a1.x, b2.x, acc[1][2]); acc[1][2] = ffma2(a1.y, b2.y, acc[1][2]);
            acc[1][3] = ffma2(a1.x, b3.x, acc[1][3]); acc[1][3] = ffma2(a1.y, b3.y, acc[1][3]);
            acc[2][0] = ffma2(a2.x, b0.x, acc[2][0]); acc[2][0] = ffma2(a2.y, b0.y, acc[2][0]);
            acc[2][1] = ffma2(a2.x, b1.x, acc[2][1]); acc[2][1] = ffma2(a2.y, b1.y, acc[2][1]);
            acc[2][2] = ffma2(a2.x, b2.x, acc[2][2]); acc[2][2] = ffma2(a2.y, b2.y, acc[2][2]);
            acc[2][3] = ffma2(a2.x, b3.x, acc[2][3]); acc[2][3] = ffma2(a2.y, b3.y, acc[2][3]);
            acc[3][0] = ffma2(a3.x, b0.x, acc[3][0]); acc[3][0] = ffma2(a3.y, b0.y, acc[3][0]);
            acc[3][1] = ffma2(a3.x, b1.x, acc[3][1]); acc[3][1] = ffma2(a3.y, b1.y, acc[3][1]);
            acc[3][2] = ffma2(a3.x, b2.x, acc[3][2]); acc[3][2] = ffma2(a3.y, b2.y, acc[3][2]);
            acc[3][3] = ffma2(a3.x, b3.x, acc[3][3]); acc[3][3] = ffma2(a3.y, b3.y, acc[3][3]);
        }
        __syncthreads();
    }
#pragma unroll
    for (int ii = 0; ii < 4; ++ii) {
        float4 o;
        float2 p0 = unpk(acc[ii][0]); o.x = p0.x + p0.y;
        float2 p1 = unpk(acc[ii][1]); o.y = p1.x + p1.y;
        float2 p2 = unpk(acc[ii][2]); o.z = p2.x + p2.y;
        float2 p3 = unpk(acc[ii][3]); o.w = p3.x + p3.y;
        *reinterpret_cast<float4*>(g_gramP + (size_t)z * 65536 +
                                   (size_t)(i0g + i0 + ii) * NMAT + j0g + j0) = o;
    }
}

// ===== W from gram partials =====
__global__ __launch_bounds__(256) void W_kernel(const float* __restrict__ bwp) {
    int i = blockIdx.x, j = threadIdx.x;
    float g = 0.f;
#pragma unroll
    for (int z = 0; z < 8; ++z) g += g_gramP[(size_t)z * 65536 + (size_t)i * NMAT + j];
    float bw = *bwp;
    float coef = -0.5f / (bw * bw);
    const float eps = 1e-7f;
    float pds = g_sq[i] + g_sq[j] - 2.f * g + 2.f * eps * (g_s[j] - g_s[i]) + eps * eps * 4096.f;
    g_W[(size_t)i * NMAT + j] = expf(coef * pds);
}

// ===== row/col sums of W =====
__global__ __launch_bounds__(256) void sums_kernel() {
    __shared__ float r1[256], r2[256];
    int k = blockIdx.x, t = threadIdx.x;
    r1[t] = g_W[(size_t)k * NMAT + t];
    r2[t] = g_W[(size_t)t * NMAT + k];
    __syncthreads();
    for (int off = 128; off > 0; off >>= 1) {
        if (t < off) { r1[t] += r1[t + off]; r2[t] += r2[t + off]; }
        __syncthreads();
    }
    if (t == 0) { g_rs[k] = r1[0]; g_cs[k] = r2[0]; }
}

// ===== numK[k,c] = sum_j W[j,k]*L[j,c] =====
__global__ __launch_bounds__(256) void numK_kernel() {
    __shared__ float Ws[64 * 64], Ls[64 * 64];
    int tid = threadIdx.x;
    int c0 = blockIdx.x * 64, k0 = blockIdx.y * 64;
    int i0 = (tid >> 4) << 2, j0 = (tid & 15) << 2;
    unsigned long long acc[4][2];
#pragma unroll
    for (int c = 0; c < 4; ++c) { acc[c][0] = 0ull; acc[c][1] = 0ull; }

    for (int jc = 0; jc < 4; ++jc) {
#pragma unroll
        for (int u = 0; u < 4; ++u) {
            int f4 = tid * 4 + u;
            int jj = f4 >> 4, q4 = f4 & 15;
            *reinterpret_cast<float4*>(Ws + jj * 64 + q4 * 4) =
                *reinterpret_cast<const float4*>(g_W + (size_t)(jc * 64 + jj) * NMAT + k0 + q4 * 4);
            *reinterpret_cast<float4*>(Ls + jj * 64 + q4 * 4) =
                *reinterpret_cast<const float4*>(g_L + (size_t)(jc * 64 + jj) * DD + c0 + q4 * 4);
        }
        __syncthreads();
#pragma unroll 8
        for (int jj = 0; jj < 64; ++jj) {
            const ulonglong2 av = *reinterpret_cast<const ulonglong2*>(Ws + jj * 64 + i0);
            const float4 bv = *reinterpret_cast<const float4*>(Ls + jj * 64 + j0);
            unsigned long long b0 = bcast2(bv.x), b1 = bcast2(bv.y);
            unsigned long long b2 = bcast2(bv.z), b3 = bcast2(bv.w);
            acc[0][0] = ffma2(av.x, b0, acc[0][0]); acc[0][1] = ffma2(av.y, b0, acc[0][1]);
            acc[1][0] = ffma2(av.x, b1, acc[1][0]); acc[1][1] = ffma2(av.y, b1, acc[1][1]);
            acc[2][0] = ffma2(av.x, b2, acc[2][0]); acc[2][1] = ffma2(av.y, b2, acc[2][1]);
            acc[3][0] = ffma2(av.x, b3, acc[3][0]); acc[3][1] = ffma2(av.y, b3, acc[3][1]);
        }
        __syncthreads();
    }
#pragma unroll
    for (int c = 0; c < 4; ++c) {
#pragma unroll
        for (int r2 = 0; r2 < 2; ++r2) {
            float2 p = unpk(acc[c][r2]);
            int kk = k0 + i0 + 2 * r2;
            int cc = c0 + j0 + c;
            g_numK[(size_t)kk * DD + cc] = p.x;
            g_numK[(size_t)(kk + 1) * DD + cc] = p.y;
        }
    }
}

// ===== cheb_exp: build Z in smem, bounds, Bessel coeffs, Clenshaw =====
__global__ __launch_bounds__(128) void cheb_exp_kernel(float* __restrict__ out) {
    extern __shared__ float sm[];
    float* Ys = sm;
    float* B1 = sm + DD;
    float* B2 = sm + 2 * DD;
    float* extra = sm + 3 * DD;
    int b = blockIdx.x, tid = threadIdx.x;
    const float* Lb = g_L + (size_t)b * DD;
    const float* Nb = g_numK + (size_t)b * DD;
    float rs_ = g_rs[b], cs_ = g_cs[b];
    float fL = 1.f - cs_ / rs_;
    float fN = 1.f / rs_;

    // Z into Ys + Gershgorin pieces (half-row per thread)
    int r = tid >> 1, q = tid & 1;
    float pa = 0.f, pd = 0.f;
#pragma unroll
    for (int u = 0; u < 8; ++u) {
        int cb = q * 32 + u * 4;
        int e = r * 64 + cb;
        float4 l = *reinterpret_cast<const float4*>(Lb + e);
        float4 n = *reinterpret_cast<const float4*>(Nb + e);
        float4 z;
        z.x = fmaf(fL, l.x, fN * n.x);
        z.y = fmaf(fL, l.y, fN * n.y);
        z.z = fmaf(fL, l.z, fN * n.z);
        z.w = fmaf(fL, l.w, fN * n.w);
        *reinterpret_cast<float4*>(Ys + e) = z;
        pa += fabsf(z.x) + fabsf(z.y) + fabsf(z.z) + fabsf(z.w);
        if (r >= cb && r < cb + 4) {
            float zz[4] = {z.x, z.y, z.z, z.w};
            pd = zz[r - cb];
        }
    }
    B1[tid] = pa;
    B1[128 + tid] = pd;
    __syncthreads();
    if (tid < 64) {
        float ra = B1[2 * tid] + B1[2 * tid + 1];
        float dv = B1[128 + 2 * tid] + B1[128 + 2 * tid + 1];
        float off = ra - fabsf(dv);
        B1[256 + tid] = dv + off;   // hi
        B1[320 + tid] = dv - off;   // lo
    }
    __syncthreads();
    if (tid == 0) {
        float lo = B1[320], hi = B1[256];
        for (int i = 1; i < 64; ++i) { lo = fminf(lo, B1[320 + i]); hi = fmaxf(hi, B1[256 + i]); }
        float m = 0.5f * (lo + hi);
        float h = 0.5f * (hi - lo) + 0.01f;
        if (h < 0.05f) h = 0.05f;
        extra[36] = m;
        extra[37] = h;
    }
    __syncthreads();
    if (tid <= K_EXP) {
        float m = extra[36], h2 = 0.5f * extra[37];
        int k = tid;
        float term = 1.f;
        for (int i = 1; i <= k; ++i) term *= h2 / (float)i;
        float ssum = term;
        for (int t = 1; t <= 48; ++t) {
            term *= (h2 * h2) / ((float)t * (float)(k + t));
            ssum += term;
            if (term < ssum * 1e-10f) break;
        }
        extra[k] = (k == 0 ? 1.f : 2.f) * expf(m) * ssum;
    }
    __syncthreads();

    const float m = extra[36], invh = 1.f / extra[37];
    scale_init(Ys, B1, B2, tid, m, invh, extra[K_EXP]);

    const int i0 = (tid >> 4) << 3, j0 = (tid & 15) << 2;
    float* Bc = B1;
    float* Bp = B2;
    for (int k = K_EXP - 1; k >= 1; --k) {
        chebstep(Ys, Bc, Bp, i0, j0, extra[k], 2.f);
        float* tp = Bc; Bc = Bp; Bp = tp;
    }
    chebstep(Ys, Bc, Bp, i0, j0, extra[0], 1.f);

    float* db = out + (size_t)b * DD;
#pragma unroll
    for (int u = 0; u < 8; ++u) {
        int e = (u * 128 + tid) * 4;
        *reinterpret_cast<float4*>(db + e) = *reinterpret_cast<const float4*>(Bp + e);
    }
}

// ================= launch =================
extern "C" void kernel_launch(void* const* d_in, const int* in_sizes, int n_in,
                              void* d_out, int out_size) {
    const float* X = (const float*)d_in[0];
    const float* bw = (const float*)d_in[1];
    float* out = (float*)d_out;
    (void)in_sizes; (void)n_in; (void)out_size;

    cudaFuncSetAttribute(cheb_log_kernel, cudaFuncAttributeMaxDynamicSharedMemorySize, SMEMX);
    cudaFuncSetAttribute(cheb_exp_kernel, cudaFuncAttributeMaxDynamicSharedMemorySize, SMEMX);

    cheb_log_kernel<<<NMAT, 128, SMEMX>>>(X);
    gram_kernel<<<dim3(4, 4, 8), 256>>>();
    W_kernel<<<NMAT, 256>>>(bw);
    sums_kernel<<<NMAT, 256>>>();
    numK_kernel<<<dim3(64, 4), 256>>>();
    cheb_exp_kernel<<<NMAT, 128, SMEMX>>>(out);
}